// round 1
// baseline (speedup 1.0000x reference)
#include <cuda_runtime.h>

// out[b,h,w] = sum_c x[b,h,w,c] * sigmoid(12*(sigmoid(5*w[h%8,w%8,c]) - thresh[h%8,w%8,c]))
// x: (32,512,512,4) fp32 NHWC, w/thresh: (1,8,8,4) fp32, out: (32,512,512,1) fp32.
//
// Streaming, DRAM-bound. Each thread: 4 consecutive pixels = 4x float4 load,
// 1x float4 store. Mask table (64 x float4) built per-block in shared memory.

#define PMASK_SLOPE 5.0f
#define SAMPLE_SLOPE 12.0f

__device__ __forceinline__ float sigmoidf(float z) {
    return 1.0f / (1.0f + __expf(-z));
}

__global__ void __launch_bounds__(256, 8)
probmask_kernel(const float4* __restrict__ x,
                const float4* __restrict__ wv,
                const float4* __restrict__ tv,
                float4* __restrict__ out,
                int n_quads)
{
    __shared__ float4 smask[64];  // [h8*8 + w8] -> per-channel mask

    int tid = threadIdx.x;
    if (tid < 64) {
        float4 w4 = wv[tid];
        float4 t4 = tv[tid];
        float4 m;
        m.x = sigmoidf(SAMPLE_SLOPE * (sigmoidf(PMASK_SLOPE * w4.x) - t4.x));
        m.y = sigmoidf(SAMPLE_SLOPE * (sigmoidf(PMASK_SLOPE * w4.y) - t4.y));
        m.z = sigmoidf(SAMPLE_SLOPE * (sigmoidf(PMASK_SLOPE * w4.z) - t4.z));
        m.w = sigmoidf(SAMPLE_SLOPE * (sigmoidf(PMASK_SLOPE * w4.w) - t4.w));
        smask[tid] = m;
    }
    __syncthreads();

    int idx = blockIdx.x * blockDim.x + tid;
    if (idx >= n_quads) return;

    // quad of 4 consecutive pixels; flat pixel index i0 = idx*4 (4-aligned)
    int i0 = idx << 2;
    // W = 512 divisible by 8: w%8 = i&7 ; h%8 = (i>>9)&7 (same for all 4 pixels? h yes,
    // since pixels are consecutive in w within a row: i0..i0+3 share (i>>9) because
    // i0 is 4-aligned and 512 is a multiple of 4 -> no row crossing within the quad).
    int h8 = (i0 >> 9) & 7;
    int wb = i0 & 7;              // 0 or 4 (4-aligned)
    int mbase = (h8 << 3) + wb;

    float4 m0 = smask[mbase + 0];
    float4 m1 = smask[mbase + 1];
    float4 m2 = smask[mbase + 2];
    float4 m3 = smask[mbase + 3];

    float4 p0 = x[i0 + 0];
    float4 p1 = x[i0 + 1];
    float4 p2 = x[i0 + 2];
    float4 p3 = x[i0 + 3];

    float4 r;
    r.x = p0.x * m0.x + p0.y * m0.y + p0.z * m0.z + p0.w * m0.w;
    r.y = p1.x * m1.x + p1.y * m1.y + p1.z * m1.z + p1.w * m1.w;
    r.z = p2.x * m2.x + p2.y * m2.y + p2.z * m2.z + p2.w * m2.w;
    r.w = p3.x * m3.x + p3.y * m3.y + p3.z * m3.z + p3.w * m3.w;

    out[idx] = r;
}

extern "C" void kernel_launch(void* const* d_in, const int* in_sizes, int n_in,
                              void* d_out, int out_size)
{
    const float4* x  = (const float4*)d_in[0];   // 32*512*512*4 fp32
    const float4* wv = (const float4*)d_in[1];   // 8*8*4 fp32
    const float4* tv = (const float4*)d_in[2];   // 8*8*4 fp32
    float4* out = (float4*)d_out;                // 32*512*512 fp32

    int n_pixels = in_sizes[0] / 4;              // 8,388,608
    int n_quads  = n_pixels / 4;                 // 2,097,152

    int threads = 256;
    int blocks = (n_quads + threads - 1) / threads;  // 8192
    probmask_kernel<<<blocks, threads>>>(x, wv, tv, out, n_quads);
}